// round 1
// baseline (speedup 1.0000x reference)
#include <cuda_runtime.h>
#include <math.h>

#define FULLMASK 0xFFFFFFFFu
#define EMAX 1280
#define NMAX 384

// ---------------- persistent device scratch (no allocations allowed) ----------
__device__ int   g_snd[EMAX];
__device__ int   g_rcv[EMAX];
__device__ float g_e[EMAX];
__device__ float g_H[2][NMAX * 5];
__device__ float g_tec[19], g_tes[19];   // cos/sin(theta_edge/2)
__device__ float g_tnc[31], g_tns[31];   // cos/sin(theta_node/2)

// ---------------- warp-register statevector gate helpers ---------------------
// State layout: amplitude index = lane_bits(high) | local_reg_bits(low).
// All masks are compile-time template parameters so register indices stay static.

template<int NR, int M>
__device__ __forceinline__ void ry_local(float (&a)[NR], float c, float s) {
#pragma unroll
    for (int r = 0; r < NR; r++) if ((r & M) == 0) {
        float x = a[r], y = a[r | M];
        a[r]     = c * x - s * y;
        a[r | M] = s * x + c * y;
    }
}

template<int NR, int L>
__device__ __forceinline__ void ry_lane(float (&a)[NR], float c, float s, unsigned lane) {
    bool hi = (lane & L) != 0;
#pragma unroll
    for (int r = 0; r < NR; r++) {
        float o = __shfl_xor_sync(FULLMASK, a[r], L);
        a[r] = hi ? (s * o + c * a[r]) : (c * a[r] - s * o);
    }
}

// CNOT: control local bit, target local bit
template<int NR, int MC, int MT>
__device__ __forceinline__ void cx_ll(float (&a)[NR]) {
#pragma unroll
    for (int r = 0; r < NR; r++) if ((r & MC) && !(r & MT)) {
        float t = a[r]; a[r] = a[r | MT]; a[r | MT] = t;
    }
}

// CNOT: control local bit, target lane bit
template<int NR, int MC, int LT>
__device__ __forceinline__ void cx_localc_lanet(float (&a)[NR]) {
#pragma unroll
    for (int r = 0; r < NR; r++) {
        float o = __shfl_xor_sync(FULLMASK, a[r], LT);
        if (r & MC) a[r] = o;
    }
}

// CNOT: control lane bit, target local bit
template<int NR, int LC, int MT>
__device__ __forceinline__ void cx_lanec_localt(float (&a)[NR], unsigned lane) {
    bool p = (lane & LC) != 0;
#pragma unroll
    for (int r = 0; r < NR; r++) if (!(r & MT)) {
        float x = a[r], y = a[r | MT];
        a[r]     = p ? y : x;
        a[r | MT] = p ? x : y;
    }
}

// CNOT: control lane bit, target lane bit
template<int NR, int LC, int LT>
__device__ __forceinline__ void cx_lanec_lanet(float (&a)[NR], unsigned lane) {
    bool p = (lane & LC) != 0;
#pragma unroll
    for (int r = 0; r < NR; r++) {
        float o = __shfl_xor_sync(FULLMASK, a[r], LT);
        if (p) a[r] = o;
    }
}

// ---------------- prep: snd/rcv extraction, H0, theta tables -----------------
__global__ void prep_kernel(const float* __restrict__ X, const float* __restrict__ Ri,
                            const float* __restrict__ Ro, const float* __restrict__ W,
                            const float* __restrict__ te, const float* __restrict__ tn,
                            int N, int E) {
    int tid = blockIdx.x * blockDim.x + threadIdx.x;
    if (tid < E) {
        float accs = 0.f, accr = 0.f;
        for (int n = 0; n < N; n++) {
            accs += Ro[(size_t)n * E + tid] * (float)n;   // one-hot -> exact index sum
            accr += Ri[(size_t)n * E + tid] * (float)n;
        }
        g_snd[tid] = (int)(accs + 0.5f);
        g_rcv[tid] = (int)(accr + 0.5f);
    }
    if (tid < N) {
        float x0 = X[tid * 3 + 0], x1 = X[tid * 3 + 1], x2 = X[tid * 3 + 2];
        float z0 = x0 * W[0] + x1 * W[2] + x2 * W[4];
        float z1 = x0 * W[1] + x1 * W[3] + x2 * W[5];
        const float TWOPI = 6.283185307179586f;
        g_H[0][tid * 5 + 0] = TWOPI / (1.f + expf(-z0));
        g_H[0][tid * 5 + 1] = TWOPI / (1.f + expf(-z1));
        g_H[0][tid * 5 + 2] = x0;
        g_H[0][tid * 5 + 3] = x1;
        g_H[0][tid * 5 + 4] = x2;
    }
    if (tid < 19) { float ss, cc; sincosf(0.5f * te[tid], &ss, &cc); g_tes[tid] = ss; g_tec[tid] = cc; }
    if (tid < 31) { float ss, cc; sincosf(0.5f * tn[tid], &ss, &cc); g_tns[tid] = ss; g_tnc[tid] = cc; }
}

// ---------------- edge circuit: 10 qubits, one warp per edge -----------------
// qubit q (0..4)  -> lane xor-mask 1<<(4-q)
// qubit q (5..9)  -> local reg mask 1<<(9-q)
__global__ void edge_kernel(int hbuf, int N, int E, float* __restrict__ out) {
    int wid = (blockIdx.x * blockDim.x + threadIdx.x) >> 5;
    unsigned lane = threadIdx.x & 31u;
    if (wid >= E) return;
    const float* H = g_H[hbuf];
    int sn = g_snd[wid], rc = g_rcv[wid];

    float c[10], s[10];
#pragma unroll
    for (int j = 0; j < 5; j++) sincosf(0.5f * H[sn * 5 + j], &s[j], &c[j]);
#pragma unroll
    for (int j = 0; j < 5; j++) sincosf(0.5f * H[rc * 5 + j], &s[5 + j], &c[5 + j]);

    // product-state init
    float lf = (lane & 16) ? s[0] : c[0];
    lf *= (lane & 8) ? s[1] : c[1];
    lf *= (lane & 4) ? s[2] : c[2];
    lf *= (lane & 2) ? s[3] : c[3];
    lf *= (lane & 1) ? s[4] : c[4];
    float a[32];
#pragma unroll
    for (int r = 0; r < 32; r++) {
        float p = lf;
        p *= (r & 16) ? s[5] : c[5];
        p *= (r & 8)  ? s[6] : c[6];
        p *= (r & 4)  ? s[7] : c[7];
        p *= (r & 2)  ? s[8] : c[8];
        p *= (r & 1)  ? s[9] : c[9];
        a[r] = p;
    }

    // EDGE_OPS
    ry_lane<32, 16>(a, g_tec[0],  g_tes[0],  lane);   // ry t0  q0
    ry_lane<32, 8>(a,  g_tec[1],  g_tes[1],  lane);   // ry t1  q1
    cx_lanec_lanet<32, 16, 8>(a, lane);               // cx 0,1
    ry_lane<32, 4>(a,  g_tec[2],  g_tes[2],  lane);   // ry t2  q2
    ry_lane<32, 2>(a,  g_tec[3],  g_tes[3],  lane);   // ry t3  q3
    cx_lanec_lanet<32, 2, 4>(a, lane);                // cx 3,2
    ry_lane<32, 1>(a,  g_tec[4],  g_tes[4],  lane);   // ry t4  q4
    ry_local<32, 16>(a, g_tec[5], g_tes[5]);          // ry t5  q5
    cx_localc_lanet<32, 16, 1>(a);                    // cx 5,4
    ry_local<32, 8>(a,  g_tec[6], g_tes[6]);          // ry t6  q6
    ry_local<32, 4>(a,  g_tec[7], g_tes[7]);          // ry t7  q7
    cx_ll<32, 8, 4>(a);                               // cx 6,7
    ry_local<32, 2>(a,  g_tec[8], g_tes[8]);          // ry t8  q8
    ry_local<32, 1>(a,  g_tec[9], g_tes[9]);          // ry t9  q9
    cx_ll<32, 2, 1>(a);                               // cx 8,9
    ry_lane<32, 8>(a,  g_tec[10], g_tes[10], lane);   // ry t10 q1
    ry_lane<32, 4>(a,  g_tec[11], g_tes[11], lane);   // ry t11 q2
    cx_lanec_lanet<32, 8, 4>(a, lane);                // cx 1,2
    ry_local<32, 4>(a,  g_tec[12], g_tes[12]);        // ry t12 q7
    ry_local<32, 1>(a,  g_tec[13], g_tes[13]);        // ry t13 q9
    cx_ll<32, 1, 4>(a);                               // cx 9,7
    ry_lane<32, 4>(a,  g_tec[14], g_tes[14], lane);   // ry t14 q2
    ry_lane<32, 1>(a,  g_tec[15], g_tes[15], lane);   // ry t15 q4
    cx_lanec_lanet<32, 4, 1>(a, lane);                // cx 2,4
    ry_lane<32, 1>(a,  g_tec[16], g_tes[16], lane);   // ry t16 q4
    ry_local<32, 4>(a,  g_tec[17], g_tes[17]);        // ry t17 q7
    cx_lanec_localt<32, 1, 4>(a, lane);               // cx 4,7
    ry_local<32, 4>(a,  g_tec[18], g_tes[18]);        // ry t18 q7

    // expz qubit 7 -> local mask 4
    float z = 0.f;
#pragma unroll
    for (int r = 0; r < 32; r++) { float v = a[r] * a[r]; z += (r & 4) ? -v : v; }
#pragma unroll
    for (int o = 16; o; o >>= 1) z += __shfl_xor_sync(FULLMASK, z, o);

    if (lane == 0) {
        float ev = 0.5f * (1.0f - z);
        g_e[wid] = ev;
        if (out) out[wid] = ev;
    }
}

// ---------------- node circuit: factorized, one warp per node ----------------
// Component A: qubits {0..7} (256 amps): q0..4 -> lane masks 16,8,4,2,1; q5,6,7 -> local 4,2,1.
// Component B: qubits {8,9,10,11,13,14} (64 amps): 8,9,10,11,13 -> lane 16,8,4,2,1; q14 -> local 1.
// Qubit 12 never entangles and is unmeasured -> traced out exactly.
__global__ void node_kernel(const float* __restrict__ X, int rbuf, int wbuf, int N, int E) {
    int wid = (blockIdx.x * blockDim.x + threadIdx.x) >> 5;
    unsigned lane = threadIdx.x & 31u;
    if (wid >= N) return;
    const float* H = g_H[rbuf];

    // deterministic message aggregation (lane-strided + butterfly, no atomics)
    float mi[5] = {0, 0, 0, 0, 0}, mo[5] = {0, 0, 0, 0, 0};
    for (int k = lane; k < E; k += 32) {
        float ev = g_e[k];
        int sn = g_snd[k], rc = g_rcv[k];
        if (rc == wid) {
            const float* hs = &H[sn * 5];
#pragma unroll
            for (int j = 0; j < 5; j++) mi[j] += ev * hs[j];
        }
        if (sn == wid) {
            const float* hr = &H[rc * 5];
#pragma unroll
            for (int j = 0; j < 5; j++) mo[j] += ev * hr[j];
        }
    }
#pragma unroll
    for (int j = 0; j < 5; j++) {
#pragma unroll
        for (int o = 16; o; o >>= 1) {
            mi[j] += __shfl_xor_sync(FULLMASK, mi[j], o);
            mo[j] += __shfl_xor_sync(FULLMASK, mo[j], o);
        }
    }

    float c[15], s[15];
#pragma unroll
    for (int j = 0; j < 5; j++) sincosf(0.5f * mi[j], &s[j], &c[j]);
#pragma unroll
    for (int j = 0; j < 5; j++) sincosf(0.5f * mo[j], &s[5 + j], &c[5 + j]);
#pragma unroll
    for (int j = 0; j < 5; j++) sincosf(0.5f * H[wid * 5 + j], &s[10 + j], &c[10 + j]);

    // ---- component A ----
    float lfA = (lane & 16) ? s[0] : c[0];
    lfA *= (lane & 8) ? s[1] : c[1];
    lfA *= (lane & 4) ? s[2] : c[2];
    lfA *= (lane & 2) ? s[3] : c[3];
    lfA *= (lane & 1) ? s[4] : c[4];
    float a[8];
#pragma unroll
    for (int r = 0; r < 8; r++) {
        float p = lfA;
        p *= (r & 4) ? s[5] : c[5];
        p *= (r & 2) ? s[6] : c[6];
        p *= (r & 1) ? s[7] : c[7];
        a[r] = p;
    }
    ry_lane<8, 16>(a, g_tnc[0],  g_tns[0],  lane);  // t0  q0
    ry_lane<8, 8>(a,  g_tnc[1],  g_tns[1],  lane);  // t1  q1
    cx_lanec_lanet<8, 16, 8>(a, lane);              // cx 0,1
    ry_lane<8, 4>(a,  g_tnc[2],  g_tns[2],  lane);  // t2  q2
    ry_lane<8, 2>(a,  g_tnc[3],  g_tns[3],  lane);  // t3  q3
    cx_lanec_lanet<8, 2, 4>(a, lane);               // cx 3,2
    ry_lane<8, 1>(a,  g_tnc[4],  g_tns[4],  lane);  // t4  q4
    ry_local<8, 4>(a, g_tnc[5],  g_tns[5]);         // t5  q5
    cx_lanec_localt<8, 1, 4>(a, lane);              // cx 4,5
    ry_local<8, 2>(a, g_tnc[6],  g_tns[6]);         // t6  q6
    ry_local<8, 1>(a, g_tnc[7],  g_tns[7]);         // t7  q7
    cx_ll<8, 1, 2>(a);                              // cx 7,6
    ry_lane<8, 8>(a,  g_tnc[15], g_tns[15], lane);  // t15 q1
    ry_lane<8, 4>(a,  g_tnc[16], g_tns[16], lane);  // t16 q2
    cx_lanec_lanet<8, 8, 4>(a, lane);               // cx 1,2
    ry_local<8, 4>(a, g_tnc[14], g_tns[14]);        // t14 q5
    ry_local<8, 2>(a, g_tnc[15], g_tns[15]);        // t15 q6
    cx_ll<8, 2, 4>(a);                              // cx 6,5
    ry_lane<8, 4>(a,  g_tnc[19], g_tns[19], lane);  // t19 q2
    ry_local<8, 4>(a, g_tnc[20], g_tns[20]);        // t20 q5
    cx_lanec_localt<8, 4, 4>(a, lane);              // cx 2,5
    ry_local<8, 4>(a, g_tnc[23], g_tns[23]);        // t23 q5
    ry_lane<8, 16>(a, g_tnc[25], g_tns[25], lane);  // t25 q0
    ry_local<8, 4>(a, g_tnc[26], g_tns[26]);        // t26 q5
    cx_lanec_localt<8, 16, 4>(a, lane);             // cx 0,5
    ry_local<8, 4>(a, g_tnc[29], g_tns[29]);        // t29 q5

    float zA = 0.f;
#pragma unroll
    for (int r = 0; r < 8; r++) { float v = a[r] * a[r]; zA += (r & 4) ? -v : v; }
#pragma unroll
    for (int o = 16; o; o >>= 1) zA += __shfl_xor_sync(FULLMASK, zA, o);

    // ---- component B ----
    float lfB = (lane & 16) ? s[8] : c[8];       // q8
    lfB *= (lane & 8) ? s[9]  : c[9];            // q9
    lfB *= (lane & 4) ? s[10] : c[10];           // q10
    lfB *= (lane & 2) ? s[11] : c[11];           // q11
    lfB *= (lane & 1) ? s[13] : c[13];           // q13
    float b[2];
    b[0] = lfB * c[14];
    b[1] = lfB * s[14];

    ry_lane<2, 16>(b, g_tnc[8],  g_tns[8],  lane);  // t8  q8
    ry_lane<2, 8>(b,  g_tnc[9],  g_tns[9],  lane);  // t9  q9
    cx_lanec_lanet<2, 16, 8>(b, lane);              // cx 8,9
    ry_lane<2, 4>(b,  g_tnc[10], g_tns[10], lane);  // t10 q10
    ry_lane<2, 2>(b,  g_tnc[11], g_tns[11], lane);  // t11 q11
    cx_lanec_lanet<2, 2, 4>(b, lane);               // cx 11,10
    ry_lane<2, 1>(b,  g_tnc[13], g_tns[13], lane);  // t13 q13
    cx_lanec_lanet<2, 16, 8>(b, lane);              // cx 8,9
    ry_local<2, 1>(b, g_tnc[14], g_tns[14]);        // t14 q14
    ry_lane<2, 8>(b,  g_tnc[16], g_tns[16], lane);  // t16 q9
    ry_lane<2, 4>(b,  g_tnc[17], g_tns[17], lane);  // t17 q10
    cx_lanec_lanet<2, 8, 4>(b, lane);               // cx 9,10
    ry_lane<2, 1>(b,  g_tnc[18], g_tns[18], lane);  // t18 q13
    ry_local<2, 1>(b, g_tnc[19], g_tns[19]);        // t19 q14
    cx_lanec_lanet<2, 8, 4>(b, lane);               // cx 9,10
    ry_lane<2, 4>(b,  g_tnc[21], g_tns[21], lane);  // t21 q10
    ry_lane<2, 1>(b,  g_tnc[22], g_tns[22], lane);  // t22 q13
    cx_lanec_lanet<2, 1, 4>(b, lane);               // cx 13,10
    ry_lane<2, 4>(b,  g_tnc[24], g_tns[24], lane);  // t24 q10
    ry_lane<2, 4>(b,  g_tnc[27], g_tns[27], lane);  // t27 q10
    ry_local<2, 1>(b, g_tnc[28], g_tns[28]);        // t28 q14
    cx_localc_lanet<2, 1, 4>(b);                    // cx 14,10
    ry_lane<2, 4>(b,  g_tnc[30], g_tns[30], lane);  // t30 q10

    float zB = (b[0] * b[0] + b[1] * b[1]) * ((lane & 4) ? -1.0f : 1.0f);
#pragma unroll
    for (int o = 16; o; o >>= 1) zB += __shfl_xor_sync(FULLMASK, zB, o);

    if (lane == 0) {
        const float PI_F = 3.14159265358979f;
        float* Hw = g_H[wbuf];
        Hw[wid * 5 + 0] = PI_F * (1.0f - zA);
        Hw[wid * 5 + 1] = PI_F * (1.0f - zB);
        Hw[wid * 5 + 2] = X[wid * 3 + 0];
        Hw[wid * 5 + 3] = X[wid * 3 + 1];
        Hw[wid * 5 + 4] = X[wid * 3 + 2];
    }
}

// ---------------- launch sequence (graph-capturable, 6 kernels) --------------
extern "C" void kernel_launch(void* const* d_in, const int* in_sizes, int n_in,
                              void* d_out, int out_size) {
    const float* X  = (const float*)d_in[0];
    const float* Ri = (const float*)d_in[1];
    const float* Ro = (const float*)d_in[2];
    const float* W  = (const float*)d_in[3];
    const float* te = (const float*)d_in[4];
    const float* tn = (const float*)d_in[5];
    int N = in_sizes[0] / 3;
    int E = in_sizes[1] / N;
    float* out = (float*)d_out;

    int pg = ((E > N ? E : N) + 255) / 256;
    int eb = (E * 32 + 255) / 256;   // one warp per edge
    int nb = (N * 32 + 255) / 256;   // one warp per node

    prep_kernel<<<pg, 256>>>(X, Ri, Ro, W, te, tn, N, E);
    edge_kernel<<<eb, 256>>>(0, N, E, nullptr);
    node_kernel<<<nb, 256>>>(X, 0, 1, N, E);
    edge_kernel<<<eb, 256>>>(1, N, E, nullptr);
    node_kernel<<<nb, 256>>>(X, 1, 0, N, E);
    edge_kernel<<<eb, 256>>>(0, N, E, out);
}

// round 3
// speedup vs baseline: 3.1638x; 3.1638x over previous
#include <cuda_runtime.h>
#include <math.h>

#define FULLMASK 0xFFFFFFFFu
#define EMAX 1280
#define NMAX 384

// ---------------- persistent device scratch ----------------------------------
__device__ int   g_snd[EMAX];
__device__ int   g_rcv[EMAX];
__device__ float g_H[2][NMAX * 5];
__device__ float g_mi[NMAX * 5];
__device__ float g_mo[NMAX * 5];
__device__ float g_tec[19], g_tes[19];   // cos/sin(theta_edge/2), used for t10..t18
__device__ float g_tnc[31], g_tns[31];   // cos/sin(theta_node/2), later gates

// ---------------- warp-register statevector gate helpers ---------------------
template<int NR, int M>
__device__ __forceinline__ void ry_local(float (&a)[NR], float c, float s) {
#pragma unroll
    for (int r = 0; r < NR; r++) if ((r & M) == 0) {
        float x = a[r], y = a[r | M];
        a[r]     = c * x - s * y;
        a[r | M] = s * x + c * y;
    }
}

template<int NR, int L>
__device__ __forceinline__ void ry_lane(float (&a)[NR], float c, float s, unsigned lane) {
    bool hi = (lane & L) != 0;
#pragma unroll
    for (int r = 0; r < NR; r++) {
        float o = __shfl_xor_sync(FULLMASK, a[r], L);
        a[r] = hi ? (s * o + c * a[r]) : (c * a[r] - s * o);
    }
}

// CNOT control local, target local: pure register permutation (zero instrs)
template<int NR, int MC, int MT>
__device__ __forceinline__ void cx_ll(float (&a)[NR]) {
#pragma unroll
    for (int r = 0; r < NR; r++) if ((r & MC) && !(r & MT)) {
        float t = a[r]; a[r] = a[r | MT]; a[r | MT] = t;
    }
}

// CNOT control lane bit, target local bit: predicated swap, no shfl
template<int NR, int LC, int MT>
__device__ __forceinline__ void cx_lanec_localt(float (&a)[NR], unsigned lane) {
    bool p = (lane & LC) != 0;
#pragma unroll
    for (int r = 0; r < NR; r++) if (!(r & MT)) {
        float x = a[r], y = a[r | MT];
        a[r]      = p ? y : x;
        a[r | MT] = p ? x : y;
    }
}

// CNOT control lane bit, target lane bit
template<int NR, int LC, int LT>
__device__ __forceinline__ void cx_lanec_lanet(float (&a)[NR], unsigned lane) {
    bool p = (lane & LC) != 0;
#pragma unroll
    for (int r = 0; r < NR; r++) {
        float o = __shfl_xor_sync(FULLMASK, a[r], LT);
        if (p) a[r] = o;
    }
}

// ---------------- prep (fused): one-hot -> index, H0, thetas, zero msgs ------
// Grid covers 2*N*E/4 threads (float4 scan of Ro then Ri); low-tid threads also
// do the small prep work.
__global__ void prep_kernel(const float* __restrict__ X, const float* __restrict__ Ri,
                            const float* __restrict__ Ro, const float* __restrict__ W,
                            const float* __restrict__ te, const float* __restrict__ tn,
                            int N, int E) {
    int t = blockIdx.x * blockDim.x + threadIdx.x;
    int quarter = (N * E) >> 2;          // N*E divisible by 4 (E=1280)
    if (t < quarter) {
        float4 v = ((const float4*)Ro)[t];
        int base = t * 4;
        if (v.x > 0.5f) g_snd[ base      % E] =  base      / E;
        if (v.y > 0.5f) g_snd[(base + 1) % E] = (base + 1) / E;
        if (v.z > 0.5f) g_snd[(base + 2) % E] = (base + 2) / E;
        if (v.w > 0.5f) g_snd[(base + 3) % E] = (base + 3) / E;
    } else if (t < 2 * quarter) {
        int u = t - quarter;
        float4 v = ((const float4*)Ri)[u];
        int base = u * 4;
        if (v.x > 0.5f) g_rcv[ base      % E] =  base      / E;
        if (v.y > 0.5f) g_rcv[(base + 1) % E] = (base + 1) / E;
        if (v.z > 0.5f) g_rcv[(base + 2) % E] = (base + 2) / E;
        if (v.w > 0.5f) g_rcv[(base + 3) % E] = (base + 3) / E;
    }
    if (t < N * 5) { g_mi[t] = 0.f; g_mo[t] = 0.f; }
    if (t < N) {
        float x0 = X[t * 3 + 0], x1 = X[t * 3 + 1], x2 = X[t * 3 + 2];
        float z0 = x0 * W[0] + x1 * W[2] + x2 * W[4];
        float z1 = x0 * W[1] + x1 * W[3] + x2 * W[5];
        const float TWOPI = 6.283185307179586f;
        g_H[0][t * 5 + 0] = TWOPI / (1.f + expf(-z0));
        g_H[0][t * 5 + 1] = TWOPI / (1.f + expf(-z1));
        g_H[0][t * 5 + 2] = x0;
        g_H[0][t * 5 + 3] = x1;
        g_H[0][t * 5 + 4] = x2;
    }
    if (t < 19) { float ss, cc; sincosf(0.5f * te[t], &ss, &cc); g_tes[t] = ss; g_tec[t] = cc; }
    if (t < 31) { float ss, cc; sincosf(0.5f * tn[t], &ss, &cc); g_tns[t] = ss; g_tnc[t] = cc; }
}

// ---------------- edge circuit: 10 qubits, one warp per edge -----------------
// First-layer RYs folded into init. Lane qubits (controls only): q0=16,q3=8,q5=4,q6=2,q8=1.
// Local qubits: q1=16, q2=8, q4=4, q7=2, q9=1. Zero shuffles in the circuit body.
__global__ void edge_kernel(int hbuf, int E, const float* __restrict__ te_raw,
                            float* __restrict__ out, int scatter) {
    int wid = (blockIdx.x * blockDim.x + threadIdx.x) >> 5;
    unsigned lane = threadIdx.x & 31u;
    if (wid >= E) return;
    const float* H = g_H[hbuf];
    int sn = g_snd[wid], rc = g_rcv[wid];

    // distributed sincos: lane j<10 computes angle of qubit j (feature + folded theta)
    float hv = 0.f;
    if (lane < 5)       hv = H[sn * 5 + lane];
    else if (lane < 10) hv = H[rc * 5 + (lane - 5)];
    float ang = (lane < 10) ? 0.5f * (hv + te_raw[lane]) : 0.f;
    float sv, cv;
    sincosf(ang, &sv, &cv);
    float s[10], c[10];
#pragma unroll
    for (int j = 0; j < 10; j++) {
        s[j] = __shfl_sync(FULLMASK, sv, j);
        c[j] = __shfl_sync(FULLMASK, cv, j);
    }

    // product-state init (lane bits: q0,q3,q5,q6,q8)
    float lf = ((lane & 16) ? s[0] : c[0]) * ((lane & 8) ? s[3] : c[3])
             * ((lane & 4) ? s[5] : c[5]) * ((lane & 2) ? s[6] : c[6])
             * ((lane & 1) ? s[8] : c[8]);
    // register bits: q1=16,q2=8,q4=4,q7=2,q9=1 — shared product tree
    float u[4] = { lf * c[1] * c[2], lf * c[1] * s[2], lf * s[1] * c[2], lf * s[1] * s[2] };
    float v[4] = { c[4] * c[7], c[4] * s[7], s[4] * c[7], s[4] * s[7] };
    float a[32];
#pragma unroll
    for (int r = 0; r < 32; r++)
        a[r] = u[(r >> 3) & 3] * v[(r >> 1) & 3] * ((r & 1) ? s[9] : c[9]);

    // remaining EDGE_OPS (all local targets)
    cx_lanec_localt<32, 16, 16>(a, lane);            // cx 0,1
    cx_lanec_localt<32, 8, 8>(a, lane);              // cx 3,2
    cx_lanec_localt<32, 4, 4>(a, lane);              // cx 5,4
    cx_lanec_localt<32, 2, 2>(a, lane);              // cx 6,7
    cx_lanec_localt<32, 1, 1>(a, lane);              // cx 8,9
    ry_local<32, 16>(a, g_tec[10], g_tes[10]);       // ry t10 q1
    ry_local<32, 8>(a,  g_tec[11], g_tes[11]);       // ry t11 q2
    cx_ll<32, 16, 8>(a);                             // cx 1,2
    ry_local<32, 2>(a,  g_tec[12], g_tes[12]);       // ry t12 q7
    ry_local<32, 1>(a,  g_tec[13], g_tes[13]);       // ry t13 q9
    cx_ll<32, 1, 2>(a);                              // cx 9,7
    ry_local<32, 8>(a,  g_tec[14], g_tes[14]);       // ry t14 q2
    ry_local<32, 4>(a,  g_tec[15], g_tes[15]);       // ry t15 q4
    cx_ll<32, 8, 4>(a);                              // cx 2,4
    ry_local<32, 4>(a,  g_tec[16], g_tes[16]);       // ry t16 q4
    ry_local<32, 2>(a,  g_tec[17], g_tes[17]);       // ry t17 q7
    cx_ll<32, 4, 2>(a);                              // cx 4,7
    ry_local<32, 2>(a,  g_tec[18], g_tes[18]);       // ry t18 q7

    // expz qubit 7 (local mask 2)
    float z = 0.f;
#pragma unroll
    for (int r = 0; r < 32; r++) { float vv = a[r] * a[r]; z += (r & 2) ? -vv : vv; }
#pragma unroll
    for (int o = 16; o; o >>= 1) z += __shfl_xor_sync(FULLMASK, z, o);
    float ev = 0.5f * (1.0f - z);     // all lanes hold ev

    if (scatter) {
        if (lane < 5)       atomicAdd(&g_mi[rc * 5 + lane],       ev * hv);
        else if (lane < 10) atomicAdd(&g_mo[sn * 5 + (lane - 5)], ev * hv);
    }
    if (out && lane == 0) out[wid] = ev;
}

// ---------------- node circuit: factorized, one warp per node ----------------
// Component A (q0..7, measure q5): lanes q0=16,q1=8,q3=4,q4=2,q7=1; local q2=4,q5=2,q6=1.
// Component B (q8,9,10,11,13,14, measure q10): lanes q8=16,q9=8,q11=4,q13=2,q14=1; local q10=1.
// Qubit 12 never entangles and is unmeasured -> traced out exactly.
__global__ void node_kernel(const float* __restrict__ X, const float* __restrict__ tn_raw,
                            int rbuf, int wbuf, int N) {
    int wid = (blockIdx.x * blockDim.x + threadIdx.x) >> 5;
    unsigned lane = threadIdx.x & 31u;
    if (wid >= N) return;
    const float* H = g_H[rbuf];

    // per-lane angle (qubit lane): 0-4: mi, 5-9: mo, 10-14: H(self); fold theta_node
    float feat = 0.f;
    if (lane < 5)        feat = g_mi[wid * 5 + lane];
    else if (lane < 10)  feat = g_mo[wid * 5 + (lane - 5)];
    else if (lane < 15)  feat = H[wid * 5 + (lane - 10)];
    float ang = (lane < 15) ? 0.5f * (feat + tn_raw[lane]) : 0.f;
    float sv, cv;
    sincosf(ang, &sv, &cv);
    __syncwarp();
    // re-zero messages for the next edge round (exclusive per-warp slots)
    if (lane < 5)       g_mi[wid * 5 + lane] = 0.f;
    else if (lane < 10) g_mo[wid * 5 + (lane - 5)] = 0.f;

    float s[15], c[15];
#pragma unroll
    for (int j = 0; j < 15; j++) {
        s[j] = __shfl_sync(FULLMASK, sv, j);
        c[j] = __shfl_sync(FULLMASK, cv, j);
    }

    // ---- component A ----
    float lfA = ((lane & 16) ? s[0] : c[0]) * ((lane & 8) ? s[1] : c[1])
              * ((lane & 4) ? s[3] : c[3]) * ((lane & 2) ? s[4] : c[4])
              * ((lane & 1) ? s[7] : c[7]);
    float a[8];
#pragma unroll
    for (int r = 0; r < 8; r++) {
        float p = lfA;
        p *= (r & 4) ? s[2] : c[2];
        p *= (r & 2) ? s[5] : c[5];
        p *= (r & 1) ? s[6] : c[6];
        a[r] = p;
    }
    cx_lanec_lanet<8, 16, 8>(a, lane);              // cx 0,1
    cx_lanec_localt<8, 4, 4>(a, lane);              // cx 3,2
    cx_lanec_localt<8, 2, 2>(a, lane);              // cx 4,5
    cx_lanec_localt<8, 1, 1>(a, lane);              // cx 7,6
    ry_lane<8, 8>(a,  g_tnc[15], g_tns[15], lane);  // t15 q1
    ry_local<8, 4>(a, g_tnc[16], g_tns[16]);        // t16 q2
    cx_lanec_localt<8, 8, 4>(a, lane);              // cx 1,2
    ry_local<8, 2>(a, g_tnc[14], g_tns[14]);        // t14 q5
    ry_local<8, 1>(a, g_tnc[15], g_tns[15]);        // t15 q6
    cx_ll<8, 1, 2>(a);                              // cx 6,5
    ry_local<8, 4>(a, g_tnc[19], g_tns[19]);        // t19 q2
    ry_local<8, 2>(a, g_tnc[20], g_tns[20]);        // t20 q5
    cx_ll<8, 4, 2>(a);                              // cx 2,5
    ry_local<8, 2>(a, g_tnc[23], g_tns[23]);        // t23 q5
    ry_lane<8, 16>(a, g_tnc[25], g_tns[25], lane);  // t25 q0
    ry_local<8, 2>(a, g_tnc[26], g_tns[26]);        // t26 q5
    cx_lanec_localt<8, 16, 2>(a, lane);             // cx 0,5
    ry_local<8, 2>(a, g_tnc[29], g_tns[29]);        // t29 q5

    float zA = 0.f;
#pragma unroll
    for (int r = 0; r < 8; r++) { float vv = a[r] * a[r]; zA += (r & 2) ? -vv : vv; }
#pragma unroll
    for (int o = 16; o; o >>= 1) zA += __shfl_xor_sync(FULLMASK, zA, o);

    // ---- component B ----
    float lfB = ((lane & 16) ? s[8] : c[8]) * ((lane & 8) ? s[9] : c[9])
              * ((lane & 4) ? s[11] : c[11]) * ((lane & 2) ? s[13] : c[13])
              * ((lane & 1) ? s[14] : c[14]);
    float b[2];
    b[0] = lfB * c[10];
    b[1] = lfB * s[10];

    cx_lanec_lanet<2, 16, 8>(b, lane);              // cx 8,9
    cx_lanec_localt<2, 4, 1>(b, lane);              // cx 11,10
    cx_lanec_lanet<2, 16, 8>(b, lane);              // cx 8,9
    ry_lane<2, 8>(b,  g_tnc[16], g_tns[16], lane);  // t16 q9
    ry_local<2, 1>(b, g_tnc[17], g_tns[17]);        // t17 q10
    cx_lanec_localt<2, 8, 1>(b, lane);              // cx 9,10
    ry_lane<2, 2>(b,  g_tnc[18], g_tns[18], lane);  // t18 q13
    ry_lane<2, 1>(b,  g_tnc[19], g_tns[19], lane);  // t19 q14
    cx_lanec_localt<2, 8, 1>(b, lane);              // cx 9,10
    ry_local<2, 1>(b, g_tnc[21], g_tns[21]);        // t21 q10
    ry_lane<2, 2>(b,  g_tnc[22], g_tns[22], lane);  // t22 q13
    cx_lanec_localt<2, 2, 1>(b, lane);              // cx 13,10
    ry_local<2, 1>(b, g_tnc[24], g_tns[24]);        // t24 q10
    ry_local<2, 1>(b, g_tnc[27], g_tns[27]);        // t27 q10
    ry_lane<2, 1>(b,  g_tnc[28], g_tns[28], lane);  // t28 q14
    cx_lanec_localt<2, 1, 1>(b, lane);              // cx 14,10
    ry_local<2, 1>(b, g_tnc[30], g_tns[30]);        // t30 q10

    float zB = b[0] * b[0] - b[1] * b[1];
#pragma unroll
    for (int o = 16; o; o >>= 1) zB += __shfl_xor_sync(FULLMASK, zB, o);

    if (lane == 0) {
        const float PI_F = 3.14159265358979f;
        float* Hw = g_H[wbuf];
        Hw[wid * 5 + 0] = PI_F * (1.0f - zA);
        Hw[wid * 5 + 1] = PI_F * (1.0f - zB);
        Hw[wid * 5 + 2] = X[wid * 3 + 0];
        Hw[wid * 5 + 3] = X[wid * 3 + 1];
        Hw[wid * 5 + 4] = X[wid * 3 + 2];
    }
}

// ---------------- launch sequence (graph-capturable, 6 kernels) --------------
extern "C" void kernel_launch(void* const* d_in, const int* in_sizes, int n_in,
                              void* d_out, int out_size) {
    const float* X  = (const float*)d_in[0];
    const float* Ri = (const float*)d_in[1];
    const float* Ro = (const float*)d_in[2];
    const float* W  = (const float*)d_in[3];
    const float* te = (const float*)d_in[4];
    const float* tn = (const float*)d_in[5];
    int N = in_sizes[0] / 3;
    int E = in_sizes[1] / N;
    float* out = (float*)d_out;

    int pg = (2 * ((N * E) / 4) + 255) / 256;   // float4 scan of Ro + Ri
    int eb = (E * 32 + 127) / 128;              // one warp per edge
    int nb = (N * 32 + 127) / 128;              // one warp per node

    prep_kernel<<<pg, 256>>>(X, Ri, Ro, W, te, tn, N, E);
    edge_kernel<<<eb, 128>>>(0, E, te, nullptr, 1);
    node_kernel<<<nb, 128>>>(X, tn, 0, 1, N);
    edge_kernel<<<eb, 128>>>(1, E, te, nullptr, 1);
    node_kernel<<<nb, 128>>>(X, tn, 1, 0, N);
    edge_kernel<<<eb, 128>>>(0, E, te, out, 0);
}